// round 8
// baseline (speedup 1.0000x reference)
#include <cuda_runtime.h>

#define CIN 16
#define DIN 64
#define HIN 96
#define WIN 96
#define DD 32
#define HH 48
#define WW 48
#define NVOX (DD*HH*WW)          /* 73728 */
#define RR 3
#define PD (DD+2*RR)             /* 38 */
#define PH (HH+2*RR)             /* 54 */
#define PW (WW+2*RR)             /* 54 */

#define N_FF (4*NVOX)
#define N_FM (4*PD*PH*PW)
#define NGRP (NVOX/2)            /* 36864 voxel-pairs */

// Pooled features, channel-grouped layout: index = ((z*H + y)*4 + q)*W + x,
// each element a float4 holding channels 4q..4q+3.
__device__ float4 g_ff[(size_t)DD*HH*4*WW];
__device__ float4 g_fm[(size_t)PD*PH*4*PW];   // zero-padded by RR on each side

// ---------------------------------------------------------------------------
// Fused pooling: one grid covers both tensors (overlaps the two DRAM streams).
// ---------------------------------------------------------------------------
__global__ void pool_kernel(const float* __restrict__ ff_in,
                            const float* __restrict__ fm_in) {
    int i = blockIdx.x * blockDim.x + threadIdx.x;
    if (i < N_FF) {
        int x = i % WW;
        int y = (i / WW) % HH;
        int z = (i / (WW * HH)) % DD;
        int q = i / NVOX;
        float s[4];
#pragma unroll
        for (int cc = 0; cc < 4; cc++) {
            int c = q * 4 + cc;
            const float* p = ff_in + (((size_t)c * DIN + 2 * z) * HIN + 2 * y) * WIN + 2 * x;
            float acc = 0.f;
#pragma unroll
            for (int dz = 0; dz < 2; dz++)
#pragma unroll
                for (int dy = 0; dy < 2; dy++) {
                    const float2 v = *(const float2*)(p + (size_t)dz * HIN * WIN + dy * WIN);
                    acc += v.x + v.y;
                }
            s[cc] = acc * 0.125f;
        }
        g_ff[((size_t)(z * HH + y) * 4 + q) * WW + x] = make_float4(s[0], s[1], s[2], s[3]);
    } else {
        int j = i - N_FF;
        if (j >= N_FM) return;
        int x = j % PW;
        int y = (j / PW) % PH;
        int z = (j / (PW * PH)) % PD;
        int q = j / (PD * PH * PW);
        int iz = z - RR, iy = y - RR, ix = x - RR;
        float s[4] = {0.f, 0.f, 0.f, 0.f};
        if (iz >= 0 && iz < DD && iy >= 0 && iy < HH && ix >= 0 && ix < WW) {
#pragma unroll
            for (int cc = 0; cc < 4; cc++) {
                int c = q * 4 + cc;
                const float* p = fm_in + (((size_t)c * DIN + 2 * iz) * HIN + 2 * iy) * WIN + 2 * ix;
                float acc = 0.f;
#pragma unroll
                for (int dz = 0; dz < 2; dz++)
#pragma unroll
                    for (int dy = 0; dy < 2; dy++) {
                        const float2 v = *(const float2*)(p + (size_t)dz * HIN * WIN + dy * WIN);
                        acc += v.x + v.y;
                    }
                s[cc] = acc * 0.125f;
            }
        }
        g_fm[((size_t)(z * PH + y) * 4 + q) * PW + x] = make_float4(s[0], s[1], s[2], s[3]);
    }
}

// ---------------------------------------------------------------------------
// Top-5 insertion (strict > keeps earliest index on ties, matching lax.top_k)
// ---------------------------------------------------------------------------
#define DEF_TOPK(P)                                                           \
    float P##v0 = -1e30f, P##v1 = -1e30f, P##v2 = -1e30f, P##v3 = -1e30f,     \
          P##v4 = -1e30f;                                                     \
    int P##q0 = 0, P##q1 = 0, P##q2 = 0, P##q3 = 0, P##q4 = 0;

#define TOPK_INS(P, cval, pidx)                                               \
    if (cval > P##v4) {                                                       \
        P##v4 = cval; P##q4 = pidx;                                           \
        if (P##v4 > P##v3) { float t = P##v4; P##v4 = P##v3; P##v3 = t;       \
                             int u = P##q4; P##q4 = P##q3; P##q3 = u; }       \
        if (P##v3 > P##v2) { float t = P##v3; P##v3 = P##v2; P##v2 = t;       \
                             int u = P##q3; P##q3 = P##q2; P##q2 = u; }       \
        if (P##v2 > P##v1) { float t = P##v2; P##v2 = P##v1; P##v1 = t;       \
                             int u = P##q2; P##q2 = P##q1; P##q1 = u; }       \
        if (P##v1 > P##v0) { float t = P##v1; P##v1 = P##v0; P##v0 = t;       \
                             int u = P##q1; P##q1 = P##q0; P##q0 = u; }       \
    }

// dot of 16-ch fixed features with moving features, sequential channel order
// (must stay sequential: matches reference summation, rel_err ~9e-8)
__device__ __forceinline__ float dot16(const float4& a0, const float4& a1,
                                       const float4& a2, const float4& a3,
                                       const float4& m0, const float4& m1,
                                       const float4& m2, const float4& m3) {
    float c = a0.x * m0.x;
    c = fmaf(a0.y, m0.y, c); c = fmaf(a0.z, m0.z, c); c = fmaf(a0.w, m0.w, c);
    c = fmaf(a1.x, m1.x, c); c = fmaf(a1.y, m1.y, c);
    c = fmaf(a1.z, m1.z, c); c = fmaf(a1.w, m1.w, c);
    c = fmaf(a2.x, m2.x, c); c = fmaf(a2.y, m2.y, c);
    c = fmaf(a2.z, m2.z, c); c = fmaf(a2.w, m2.w, c);
    c = fmaf(a3.x, m3.x, c); c = fmaf(a3.y, m3.y, c);
    c = fmaf(a3.z, m3.z, c); c = fmaf(a3.w, m3.w, c);
    return c;
}

// scatter one top-k winner into both output levels
__device__ __forceinline__ void scatter_one(float* __restrict__ out,
                                            int z, int y, int x,
                                            float v, int pj) {
    const float sc[4] = {1.0f, 0.5f, 0.25f, 0.125f};
    int oz = pj / 49 - 3;
    int oy = (pj / 7) % 7 - 3;
    int ox = pj % 7 - 3;

    // level 0: integer displacement, single unit-weight corner
    {
        int tz = min(max(z + oz, 0), DD - 1);
        int ty = min(max(y + oy, 0), HH - 1);
        int tx = min(max(x + ox, 0), WW - 1);
        atomicAdd(&out[(tz * HH + ty) * WW + tx], v);
    }
    // level 1: displacement * 0.5, trilinear splat
    {
        int fz = oz >> 1, fy = oy >> 1, fx = ox >> 1;   // floor(o/2)
        int ez = oz & 1, ey = oy & 1, ex = ox & 1;      // odd -> two corners
        float wv = v * sc[ez + ey + ex];
        float* out1 = out + NVOX;
#pragma unroll
        for (int cz = 0; cz < 2; cz++) {
            if (cz > ez) break;
            int tz = min(max(z + fz + cz, 0), DD - 1);
#pragma unroll
            for (int cy = 0; cy < 2; cy++) {
                if (cy > ey) break;
                int ty = min(max(y + fy + cy, 0), HH - 1);
#pragma unroll
                for (int cx = 0; cx < 2; cx++) {
                    if (cx > ex) break;
                    int tx = min(max(x + fx + cx, 0), WW - 1);
                    atomicAdd(&out1[(tz * HH + ty) * WW + tx], wv);
                }
            }
        }
    }
}

// merge 4 partial top-5 lists (20 smem entries) -> global top-5, then scatter.
// Tie-break: equal values -> smaller flat window index p (matches lax.top_k).
__device__ __forceinline__ void merge_scatter(const float* __restrict__ sv,
                                              const int* __restrict__ si,
                                              float* __restrict__ out,
                                              int z, int y, int x) {
    unsigned used = 0;
#pragma unroll
    for (int k = 0; k < 5; k++) {
        float best = -3e38f;
        int bestp = 0x7fffffff;
        int bi = 0;
        for (int i = 0; i < 20; i++) {
            if (used & (1u << i)) continue;
            float v = sv[i];
            int p = si[i];
            if (v > best || (v == best && p < bestp)) { best = v; bestp = p; bi = i; }
        }
        used |= 1u << bi;
        scatter_one(out, z, y, x, best, bestp);
    }
}

// ---------------------------------------------------------------------------
// Correlation + top-5 + scatter.
// A voxel-pair (z, z+1) at (y, x) is handled by FOUR threads: same lane in
// the block's four warps (warp index == sub == which 2 of the 8 fm slices).
// Lanes within a warp map to 32 CONSECUTIVE voxel-groups -> consecutive x ->
// fully coalesced 512B loads (this was broken in R6: sub lived in lane bits).
// doA/doB are warp-uniform so dead slices are skipped, not predicated.
// Partial top-5 lists merge through shared memory after __syncthreads().
// ---------------------------------------------------------------------------
__global__ void __launch_bounds__(128) corr_scatter_kernel(float* __restrict__ out) {
    __shared__ float sv[2][32][20];
    __shared__ int   si[2][32][20];

    const int lane = threadIdx.x & 31;
    const int sub  = threadIdx.x >> 5;           // 0..3, warp-uniform
    const int grp  = blockIdx.x * 32 + lane;     // grid sized exactly: no guard
    const int x = grp % WW;
    const int y = (grp / WW) % HH;
    const int z = (grp / (WW * HH)) * 2;

    const float4* fa = &g_ff[((size_t)(z * HH + y) * 4) * WW + x];
    float4 a0 = fa[0], a1 = fa[WW], a2 = fa[2 * WW], a3 = fa[3 * WW];
    const float4* fb = &g_ff[((size_t)((z + 1) * HH + y) * 4) * WW + x];
    float4 b0 = fb[0], b1 = fb[WW], b2 = fb[2 * WW], b3 = fb[3 * WW];

    DEF_TOPK(A)
    DEF_TOPK(B)

#pragma unroll
    for (int s = 0; s < 2; s++) {
        const int pza = sub * 2 + s;             // absolute slice: fm[z+pza-3]
        const bool doA = (pza < 7);              // output z   uses pz = pza
        const bool doB = (pza >= 1);             // output z+1 uses pz = pza-1
        const int baseA = pza * 49;
        const int baseB = (pza - 1) * 49;
        for (int py = 0; py < 7; py++) {
            const float4* mb =
                &g_fm[((size_t)((z + pza) * PH + (y + py)) * 4) * PW + x];
            const int rowA = baseA + py * 7;
            const int rowB = baseB + py * 7;
#pragma unroll
            for (int px = 0; px < 7; px++) {
                float4 m0 = mb[px];
                float4 m1 = mb[PW + px];
                float4 m2 = mb[2 * PW + px];
                float4 m3 = mb[3 * PW + px];
                if (doA) {
                    float c = dot16(a0, a1, a2, a3, m0, m1, m2, m3);
                    TOPK_INS(A, c, rowA + px)
                }
                if (doB) {
                    float c = dot16(b0, b1, b2, b3, m0, m1, m2, m3);
                    TOPK_INS(B, c, rowB + px)
                }
            }
        }
    }

    // publish partial lists (each thread: 5 A-entries, 5 B-entries)
    float* pA = &sv[0][lane][sub * 5];
    int*   iA = &si[0][lane][sub * 5];
    pA[0] = Av0; pA[1] = Av1; pA[2] = Av2; pA[3] = Av3; pA[4] = Av4;
    iA[0] = Aq0; iA[1] = Aq1; iA[2] = Aq2; iA[3] = Aq3; iA[4] = Aq4;
    float* pB = &sv[1][lane][sub * 5];
    int*   iB = &si[1][lane][sub * 5];
    pB[0] = Bv0; pB[1] = Bv1; pB[2] = Bv2; pB[3] = Bv3; pB[4] = Bv4;
    iB[0] = Bq0; iB[1] = Bq1; iB[2] = Bq2; iB[3] = Bq3; iB[4] = Bq4;

    __syncthreads();

    if (sub == 0) merge_scatter(&sv[0][lane][0], &si[0][lane][0], out, z, y, x);
    if (sub == 1) merge_scatter(&sv[1][lane][0], &si[1][lane][0], out, z + 1, y, x);
}

// ---------------------------------------------------------------------------
extern "C" void kernel_launch(void* const* d_in, const int* in_sizes, int n_in,
                              void* d_out, int out_size) {
    (void)in_sizes; (void)n_in;
    const float* feat_fix = (const float*)d_in[0];
    const float* feat_mov = (const float*)d_in[1];
    float* out = (float*)d_out;

    cudaMemsetAsync(out, 0, (size_t)out_size * sizeof(float), 0);

    int t = 256;
    int pool_total = N_FF + N_FM;
    pool_kernel<<<(pool_total + t - 1) / t, t>>>(feat_fix, feat_mov);

    // one block (128 threads = 4 warps) per 32 voxel-pairs; NGRP/32 = 1152
    corr_scatter_kernel<<<NGRP / 32, 128>>>(out);
}

// round 9
// speedup vs baseline: 1.2695x; 1.2695x over previous
#include <cuda_runtime.h>

#define CIN 16
#define DIN 64
#define HIN 96
#define WIN 96
#define DD 32
#define HH 48
#define WW 48
#define NVOX (DD*HH*WW)          /* 73728 */
#define RR 3
#define PD (DD+2*RR)             /* 38 */
#define PH (HH+2*RR)             /* 54 */
#define PW (WW+2*RR)             /* 54 */

#define N_FF (4*NVOX)
#define N_FM (4*PD*PH*PW)

// Pooled features, channel-grouped layout: index = ((z*H + y)*4 + q)*W + x,
// each element a float4 holding channels 4q..4q+3.
__device__ float4 g_ff[(size_t)DD*HH*4*WW];
__device__ float4 g_fm[(size_t)PD*PH*4*PW];   // zero-padded by RR on each side

// ---------------------------------------------------------------------------
// Fused pooling: one grid covers both tensors (overlaps the two DRAM streams).
// ---------------------------------------------------------------------------
__global__ void pool_kernel(const float* __restrict__ ff_in,
                            const float* __restrict__ fm_in) {
    int i = blockIdx.x * blockDim.x + threadIdx.x;
    if (i < N_FF) {
        int x = i % WW;
        int y = (i / WW) % HH;
        int z = (i / (WW * HH)) % DD;
        int q = i / NVOX;
        float s[4];
#pragma unroll
        for (int cc = 0; cc < 4; cc++) {
            int c = q * 4 + cc;
            const float* p = ff_in + (((size_t)c * DIN + 2 * z) * HIN + 2 * y) * WIN + 2 * x;
            float acc = 0.f;
#pragma unroll
            for (int dz = 0; dz < 2; dz++)
#pragma unroll
                for (int dy = 0; dy < 2; dy++) {
                    const float2 v = *(const float2*)(p + (size_t)dz * HIN * WIN + dy * WIN);
                    acc += v.x + v.y;
                }
            s[cc] = acc * 0.125f;
        }
        g_ff[((size_t)(z * HH + y) * 4 + q) * WW + x] = make_float4(s[0], s[1], s[2], s[3]);
    } else {
        int j = i - N_FF;
        if (j >= N_FM) return;
        int x = j % PW;
        int y = (j / PW) % PH;
        int z = (j / (PW * PH)) % PD;
        int q = j / (PD * PH * PW);
        int iz = z - RR, iy = y - RR, ix = x - RR;
        float s[4] = {0.f, 0.f, 0.f, 0.f};
        if (iz >= 0 && iz < DD && iy >= 0 && iy < HH && ix >= 0 && ix < WW) {
#pragma unroll
            for (int cc = 0; cc < 4; cc++) {
                int c = q * 4 + cc;
                const float* p = fm_in + (((size_t)c * DIN + 2 * iz) * HIN + 2 * iy) * WIN + 2 * ix;
                float acc = 0.f;
#pragma unroll
                for (int dz = 0; dz < 2; dz++)
#pragma unroll
                    for (int dy = 0; dy < 2; dy++) {
                        const float2 v = *(const float2*)(p + (size_t)dz * HIN * WIN + dy * WIN);
                        acc += v.x + v.y;
                    }
                s[cc] = acc * 0.125f;
            }
        }
        g_fm[((size_t)(z * PH + y) * 4 + q) * PW + x] = make_float4(s[0], s[1], s[2], s[3]);
    }
}

// ---------------------------------------------------------------------------
// Top-5 insertion (strict > keeps earliest index on ties, matching lax.top_k)
// ---------------------------------------------------------------------------
#define DEF_TOPK(P)                                                           \
    float P##v0 = -1e30f, P##v1 = -1e30f, P##v2 = -1e30f, P##v3 = -1e30f,     \
          P##v4 = -1e30f;                                                     \
    int P##q0 = 0, P##q1 = 0, P##q2 = 0, P##q3 = 0, P##q4 = 0;

#define TOPK_INS(P, cval, pidx)                                               \
    if (cval > P##v4) {                                                       \
        P##v4 = cval; P##q4 = pidx;                                           \
        if (P##v4 > P##v3) { float t = P##v4; P##v4 = P##v3; P##v3 = t;       \
                             int u = P##q4; P##q4 = P##q3; P##q3 = u; }       \
        if (P##v3 > P##v2) { float t = P##v3; P##v3 = P##v2; P##v2 = t;       \
                             int u = P##q3; P##q3 = P##q2; P##q2 = u; }       \
        if (P##v2 > P##v1) { float t = P##v2; P##v2 = P##v1; P##v1 = t;       \
                             int u = P##q2; P##q2 = P##q1; P##q1 = u; }       \
        if (P##v1 > P##v0) { float t = P##v1; P##v1 = P##v0; P##v0 = t;       \
                             int u = P##q1; P##q1 = P##q0; P##q0 = u; }       \
    }

// dot of 16-ch fixed features with moving features, sequential channel order
// (must stay sequential: matches reference summation, rel_err ~9e-8)
__device__ __forceinline__ float dot16(const float4& a0, const float4& a1,
                                       const float4& a2, const float4& a3,
                                       const float4& m0, const float4& m1,
                                       const float4& m2, const float4& m3) {
    float c = a0.x * m0.x;
    c = fmaf(a0.y, m0.y, c); c = fmaf(a0.z, m0.z, c); c = fmaf(a0.w, m0.w, c);
    c = fmaf(a1.x, m1.x, c); c = fmaf(a1.y, m1.y, c);
    c = fmaf(a1.z, m1.z, c); c = fmaf(a1.w, m1.w, c);
    c = fmaf(a2.x, m2.x, c); c = fmaf(a2.y, m2.y, c);
    c = fmaf(a2.z, m2.z, c); c = fmaf(a2.w, m2.w, c);
    c = fmaf(a3.x, m3.x, c); c = fmaf(a3.y, m3.y, c);
    c = fmaf(a3.z, m3.z, c); c = fmaf(a3.w, m3.w, c);
    return c;
}

// scatter one top-k winner into both output levels
__device__ __forceinline__ void scatter_one(float* __restrict__ out,
                                            int z, int y, int x,
                                            float v, int pj) {
    const float sc[4] = {1.0f, 0.5f, 0.25f, 0.125f};
    int oz = pj / 49 - 3;
    int oy = (pj / 7) % 7 - 3;
    int ox = pj % 7 - 3;

    // level 0: integer displacement, single unit-weight corner
    {
        int tz = min(max(z + oz, 0), DD - 1);
        int ty = min(max(y + oy, 0), HH - 1);
        int tx = min(max(x + ox, 0), WW - 1);
        atomicAdd(&out[(tz * HH + ty) * WW + tx], v);
    }
    // level 1: displacement * 0.5, trilinear splat
    {
        int fz = oz >> 1, fy = oy >> 1, fx = ox >> 1;   // floor(o/2)
        int ez = oz & 1, ey = oy & 1, ex = ox & 1;      // odd -> two corners
        float wv = v * sc[ez + ey + ex];
        float* out1 = out + NVOX;
#pragma unroll
        for (int cz = 0; cz < 2; cz++) {
            if (cz > ez) break;
            int tz = min(max(z + fz + cz, 0), DD - 1);
#pragma unroll
            for (int cy = 0; cy < 2; cy++) {
                if (cy > ey) break;
                int ty = min(max(y + fy + cy, 0), HH - 1);
#pragma unroll
                for (int cx = 0; cx < 2; cx++) {
                    if (cx > ex) break;
                    int tx = min(max(x + fx + cx, 0), WW - 1);
                    atomicAdd(&out1[(tz * HH + ty) * WW + tx], wv);
                }
            }
        }
    }
}

// merge 2 partial top-5 lists (10 smem entries) -> global top-5, then scatter.
// Tie-break: equal values -> smaller flat window index p (matches lax.top_k).
__device__ __forceinline__ void merge_scatter10(const float* __restrict__ sv,
                                                const int* __restrict__ si,
                                                float* __restrict__ out,
                                                int z, int y, int x) {
    unsigned used = 0;
#pragma unroll
    for (int k = 0; k < 5; k++) {
        float best = -3e38f;
        int bestp = 0x7fffffff;
        int bi = 0;
#pragma unroll
        for (int i = 0; i < 10; i++) {
            if (used & (1u << i)) continue;
            float v = sv[i];
            int p = si[i];
            if (v > best || (v == best && p < bestp)) { best = v; bestp = p; bi = i; }
        }
        used |= 1u << bi;
        scatter_one(out, z, y, x, best, bestp);
    }
}

// ---------------------------------------------------------------------------
// Correlation + top-5 + scatter.  ONE output voxel per thread (single top-5
// list + single 16-ch feature set -> ~60 regs, ~2.3x the resident warps of
// the 98-reg z-sharing version; R8 ncu showed occ=21% latency-bound with all
// pipes < 50%).  The 49 (pz,py) window rows are split 25/24 across the two
// warps of a warp-pair (warp-uniform -> no divergence); lanes keep mapping to
// 32 consecutive x (fully coalesced 512B row loads).  The two partial top-5
// lists per voxel merge in shared memory.
// ---------------------------------------------------------------------------
__global__ void __launch_bounds__(128) corr_scatter_kernel(float* __restrict__ out) {
    __shared__ float sv[2][32][10];
    __shared__ int   si[2][32][10];

    const int lane = threadIdx.x & 31;
    const int half = (threadIdx.x >> 5) & 1;     // which row-range of window
    const int set  = threadIdx.x >> 6;           // which 32-voxel group
    const int grp  = blockIdx.x * 64 + set * 32 + lane;  // exact grid: no guard
    const int x = grp % WW;
    const int y = (grp / WW) % HH;
    const int z = grp / (WW * HH);

    const float4* fa = &g_ff[((size_t)(z * HH + y) * 4) * WW + x];
    float4 a0 = fa[0], a1 = fa[WW], a2 = fa[2 * WW], a3 = fa[3 * WW];

    DEF_TOPK(A)

    const int r0 = half ? 25 : 0;                // rows 0-24 / 25-48 (175/168)
    const int r1 = half ? 49 : 25;
    for (int r = r0; r < r1; r++) {
        const int pz = r / 7;                    // const-div -> mul/shift
        const int py = r % 7;
        const float4* mb =
            &g_fm[((size_t)((z + pz) * PH + (y + py)) * 4) * PW + x];
        const int rowp = r * 7;                  // p = pz*49 + py*7 + px
#pragma unroll
        for (int px = 0; px < 7; px++) {
            float4 m0 = mb[px];
            float4 m1 = mb[PW + px];
            float4 m2 = mb[2 * PW + px];
            float4 m3 = mb[3 * PW + px];
            float c = dot16(a0, a1, a2, a3, m0, m1, m2, m3);
            TOPK_INS(A, c, rowp + px)
        }
    }

    // publish partial list
    float* pv = &sv[set][lane][half * 5];
    int*   pi = &si[set][lane][half * 5];
    pv[0] = Av0; pv[1] = Av1; pv[2] = Av2; pv[3] = Av3; pv[4] = Av4;
    pi[0] = Aq0; pi[1] = Aq1; pi[2] = Aq2; pi[3] = Aq3; pi[4] = Aq4;

    __syncthreads();

    if (half == 0)
        merge_scatter10(&sv[set][lane][0], &si[set][lane][0], out, z, y, x);
}

// ---------------------------------------------------------------------------
extern "C" void kernel_launch(void* const* d_in, const int* in_sizes, int n_in,
                              void* d_out, int out_size) {
    (void)in_sizes; (void)n_in;
    const float* feat_fix = (const float*)d_in[0];
    const float* feat_mov = (const float*)d_in[1];
    float* out = (float*)d_out;

    cudaMemsetAsync(out, 0, (size_t)out_size * sizeof(float), 0);

    int t = 256;
    int pool_total = N_FF + N_FM;
    pool_kernel<<<(pool_total + t - 1) / t, t>>>(feat_fix, feat_mov);

    // 128 threads = 2 voxel-sets of 32, 2 window-halves; NVOX/64 = 1152 blocks
    corr_scatter_kernel<<<NVOX / 64, 128>>>(out);
}